// round 2
// baseline (speedup 1.0000x reference)
#include <cuda_runtime.h>

// Problem constants
#define Bq    16384
#define Dd    128
#define Hh    4
#define Ee    8
#define Nn    65536        // B*H tokens
#define OD    32           // ODIM = D/H
#define NSLOT 131072       // Nn * TOPK
#define NGB   512          // gating blocks (128 tokens each)

// ---------------- device scratch (no allocs allowed) ----------------
__device__ float g_tok [Nn * Dd];      // 32 MB : query tokens [N,128]
__device__ float g_gate[Nn * Dd];      // 32 MB : gate tokens  [N,128]
__device__ int   g_topi [NSLOT];
__device__ float g_topw [NSLOT];
__device__ int   g_srank[NSLOT];       // rank within gating block per (token,slot)
__device__ int   g_blkcnt [NGB * Ee];
__device__ int   g_blkbase[NGB * Ee];  // per-expert exclusive prefix over blocks
__device__ int   g_off[Ee + 1];
__device__ int   g_count[Ee];
__device__ int   g_tileoff[Ee + 1];
__device__ float g_sump[Ee];
__device__ int   g_cnt1[Ee];
__device__ float g_aux;
__device__ int   g_perm[NSLOT];        // expert-sorted list of (token*2+slot)
__device__ float g_ys[(size_t)NSLOT * OD]; // 16 MB per-slot weighted expert outputs

// ---------------- init ----------------
__global__ void k_init() {
    int t = threadIdx.x;
    if (t < Ee) { g_sump[t] = 0.f; g_cnt1[t] = 0; }
}

// ---------------- projection GEMM: out[16384,512] = X[16384,128] @ W[128,512] + b ----
// block tile 128(M) x 64(N), K=128 fully smem-resident. 256 threads, 8x4 micro.
__global__ void k_proj(const float* __restrict__ X, const float* __restrict__ W,
                       const float* __restrict__ bias, float* __restrict__ out) {
    extern __shared__ float sm[];
    float* As = sm;               // 128 x 132 (pad keeps 2 ty-groups on distinct banks)
    float* Bs = sm + 128 * 132;   // 128 x 64
    const int tid = threadIdx.x;
    const int m0 = blockIdx.y * 128;
    const int n0 = blockIdx.x * 64;

    for (int i = tid; i < 128 * 32; i += 256) {
        int r = i >> 5, c = (i & 31) << 2;
        *(float4*)(As + r * 132 + c) = *(const float4*)(X + (size_t)(m0 + r) * Dd + c);
    }
    for (int i = tid; i < 128 * 16; i += 256) {
        int r = i >> 4, c = (i & 15) << 2;
        *(float4*)(Bs + r * 64 + c) = *(const float4*)(W + (size_t)r * 512 + n0 + c);
    }
    __syncthreads();

    const int tx = tid & 15, ty = tid >> 4;
    float acc[8][4];
#pragma unroll
    for (int i = 0; i < 8; i++)
#pragma unroll
        for (int j = 0; j < 4; j++) acc[i][j] = 0.f;

    const float* Ap = As + ty * 132;   // rows ty + 16*i  (bank-friendly interleave)
    const float* Bp = Bs + tx * 4;
#pragma unroll 8
    for (int k = 0; k < 128; k++) {
        float4 b = *(const float4*)(Bp + k * 64);
#pragma unroll
        for (int i = 0; i < 8; i++) {
            float a = Ap[(i * 16) * 132 + k];
            acc[i][0] = fmaf(a, b.x, acc[i][0]);
            acc[i][1] = fmaf(a, b.y, acc[i][1]);
            acc[i][2] = fmaf(a, b.z, acc[i][2]);
            acc[i][3] = fmaf(a, b.w, acc[i][3]);
        }
    }
    float4 bv = *(const float4*)(bias + n0 + tx * 4);
#pragma unroll
    for (int i = 0; i < 8; i++) {
        int m = m0 + ty + i * 16;
        float4 o;
        o.x = acc[i][0] + bv.x; o.y = acc[i][1] + bv.y;
        o.z = acc[i][2] + bv.z; o.w = acc[i][3] + bv.w;
        *(float4*)(out + (size_t)m * 512 + n0 + tx * 4) = o;
    }
}

// ---------------- gating: softmax over 8 logits, top-2, ranks + aux stats ----------
// 512 blocks x 256 threads; warp per token, 16 tokens per warp.
__global__ void k_gate(const float* __restrict__ Wg) {
    __shared__ int   srank[Ee];
    __shared__ float ssum [Ee];
    __shared__ int   scnt1[Ee];
    const int tid = threadIdx.x;
    if (tid < Ee) { srank[tid] = 0; ssum[tid] = 0.f; scnt1[tid] = 0; }
    __syncthreads();

    const int lane = tid & 31, warp = tid >> 5;
    float wr[4][8];
#pragma unroll
    for (int i = 0; i < 4; i++)
#pragma unroll
        for (int e = 0; e < 8; e++)
            wr[i][e] = Wg[(lane * 4 + i) * 8 + e];

    float lsum[8];
#pragma unroll
    for (int e = 0; e < 8; e++) lsum[e] = 0.f;

    const int wg = blockIdx.x * 8 + warp;
    for (int it = 0; it < 16; it++) {
        int n = wg * 16 + it;
        float4 gv = *(const float4*)(g_gate + (size_t)n * 128 + lane * 4);
        float p[8];
#pragma unroll
        for (int e = 0; e < 8; e++)
            p[e] = gv.x * wr[0][e] + gv.y * wr[1][e] + gv.z * wr[2][e] + gv.w * wr[3][e];
#pragma unroll
        for (int off = 16; off; off >>= 1)
#pragma unroll
            for (int e = 0; e < 8; e++)
                p[e] += __shfl_xor_sync(0xffffffffu, p[e], off);
        // softmax
        float mx = p[0];
#pragma unroll
        for (int e = 1; e < 8; e++) mx = fmaxf(mx, p[e]);
        float s = 0.f;
#pragma unroll
        for (int e = 0; e < 8; e++) { p[e] = __expf(p[e] - mx); s += p[e]; }
        float inv = 1.f / s;
#pragma unroll
        for (int e = 0; e < 8; e++) p[e] *= inv;
        // top-2 (ties -> lowest index, matching lax.top_k)
        int i1 = 0; float v1 = p[0];
#pragma unroll
        for (int e = 1; e < 8; e++) if (p[e] > v1) { v1 = p[e]; i1 = e; }
        int i2 = -1; float v2 = -1e30f;
#pragma unroll
        for (int e = 0; e < 8; e++) if (e != i1 && p[e] > v2) { v2 = p[e]; i2 = e; }
#pragma unroll
        for (int e = 0; e < 8; e++) lsum[e] += p[e];

        if (lane == 0) {
            atomicAdd(&scnt1[i1], 1);
            int r1 = atomicAdd(&srank[i1], 1);
            int r2 = atomicAdd(&srank[i2], 1);
            float wsum = v1 + v2;
            g_topi[2 * n]     = i1;  g_topi[2 * n + 1] = i2;
            g_topw[2 * n]     = v1 / wsum;
            g_topw[2 * n + 1] = v2 / wsum;
            g_srank[2 * n]     = r1;
            g_srank[2 * n + 1] = r2;
        }
    }
    if (lane == 0)
#pragma unroll
        for (int e = 0; e < 8; e++) atomicAdd(&ssum[e], lsum[e]);
    __syncthreads();
    if (tid < Ee) {
        g_blkcnt[blockIdx.x * Ee + tid] = srank[tid];
        atomicAdd(&g_sump[tid], ssum[tid]);
        atomicAdd(&g_cnt1[tid], scnt1[tid]);
    }
}

// ---------------- phase2: prefix sums, offsets, tile map, aux loss ----------------
__global__ void k_phase2() {
    const int tid = threadIdx.x;
    if (tid < Ee) {
        int base = 0;
        for (int b = 0; b < NGB; b++) {
            int c = g_blkcnt[b * Ee + tid];
            g_blkbase[b * Ee + tid] = base;
            base += c;
        }
        g_count[tid] = base;
    }
    __syncthreads();
    if (tid == 0) {
        int off = 0, toff = 0;
        for (int e = 0; e < Ee; e++) {
            g_off[e] = off; g_tileoff[e] = toff;
            off  += g_count[e];
            toff += (g_count[e] + 63) >> 6;
        }
        g_off[Ee] = off; g_tileoff[Ee] = toff;
        float aux = 0.f;
        for (int e = 0; e < Ee; e++)
            aux += (float)g_cnt1[e] * g_sump[e];
        g_aux = (float)Ee * aux / ((float)Nn * (float)Nn);
    }
}

// ---------------- scatter tokens into expert-sorted list ----------------
__global__ void k_scatter() {
    int idx = blockIdx.x * blockDim.x + threadIdx.x;
    if (idx >= NSLOT) return;
    int e = g_topi[idx];
    int n = idx >> 1;
    int pos = g_off[e] + g_blkbase[(n >> 7) * Ee + e] + g_srank[idx];
    g_perm[pos] = idx;
}

// ---------------- fused expert MLP: gather -> GEMM1+ReLU -> GEMM2 -> weighted store
// one CTA = 64 (token,slot) entries of one expert. 256 threads.
__global__ void k_expert(const float* __restrict__ W1, const float* __restrict__ b1,
                         const float* __restrict__ W2, const float* __restrict__ b2) {
    extern __shared__ float sm[];
    float* As  = sm;                   // 64 x 132 : tokens, later reused for h
    float* W1s = sm + 8448;            // 64 x 128 : W1 k-chunk
    float* W2s = sm + 8448 + 8192;     // 128 x 32
    int*   sEnc = (int*)(sm + 20736);  // 64
    float* sW   = sm + 20800;          // 64
    const int tid = threadIdx.x;

    const int t = blockIdx.x;
    if (t >= g_tileoff[Ee]) return;
    int e = 0;
#pragma unroll
    for (int i = 0; i < Ee - 1; i++)
        if (t >= g_tileoff[e + 1]) e++;
    const int tile = t - g_tileoff[e];
    const int i0 = tile << 6;
    const int nvalid = min(64, g_count[e] - i0);

    if (tid < 64) {
        int j = g_off[e] + i0 + tid;
        if (j > NSLOT - 1) j = NSLOT - 1;   // tail rows: safe garbage, never stored
        int enc = g_perm[j];
        sEnc[tid] = enc;
        sW[tid]   = g_topw[enc];
    }
    __syncthreads();

    for (int i = tid; i < 64 * 32; i += 256) {
        int r = i >> 5, c = (i & 31) << 2;
        *(float4*)(As + r * 132 + c) =
            *(const float4*)(g_tok + (size_t)(sEnc[r] >> 1) * 128 + c);
    }
    const float* W2e = W2 + (size_t)e * Dd * OD;
    for (int i = tid; i < 1024; i += 256)
        ((float4*)W2s)[i] = ((const float4*)W2e)[i];

    const int tx = tid & 15, ty = tid >> 4;
    float acc[4][8];
#pragma unroll
    for (int i = 0; i < 4; i++)
#pragma unroll
        for (int j = 0; j < 8; j++) acc[i][j] = 0.f;

    const float* W1e = W1 + (size_t)e * Dd * Dd;
#pragma unroll
    for (int kc = 0; kc < 2; kc++) {
        for (int i = tid; i < 64 * 32; i += 256) {
            int r = i >> 5, c = (i & 31) << 2;
            *(float4*)(W1s + r * 128 + c) =
                *(const float4*)(W1e + (size_t)(kc * 64 + r) * 128 + c);
        }
        __syncthreads();
#pragma unroll 8
        for (int kk = 0; kk < 64; kk++) {
            int k = kc * 64 + kk;
            float4 b0 = *(const float4*)(W1s + kk * 128 + tx * 8);
            float4 b1v = *(const float4*)(W1s + kk * 128 + tx * 8 + 4);
#pragma unroll
            for (int i = 0; i < 4; i++) {
                float a = As[(ty * 4 + i) * 132 + k];
                acc[i][0] = fmaf(a, b0.x, acc[i][0]);
                acc[i][1] = fmaf(a, b0.y, acc[i][1]);
                acc[i][2] = fmaf(a, b0.z, acc[i][2]);
                acc[i][3] = fmaf(a, b0.w, acc[i][3]);
                acc[i][4] = fmaf(a, b1v.x, acc[i][4]);
                acc[i][5] = fmaf(a, b1v.y, acc[i][5]);
                acc[i][6] = fmaf(a, b1v.z, acc[i][6]);
                acc[i][7] = fmaf(a, b1v.w, acc[i][7]);
            }
        }
        __syncthreads();
    }

    // h = relu(acc + b1), stored back into As (token data no longer needed)
    float bb[8];
    const float* b1e = b1 + e * Dd;
#pragma unroll
    for (int j = 0; j < 8; j++) bb[j] = b1e[tx * 8 + j];
#pragma unroll
    for (int i = 0; i < 4; i++) {
        int r = ty * 4 + i;
        float4 h0, h1;
        h0.x = fmaxf(acc[i][0] + bb[0], 0.f);
        h0.y = fmaxf(acc[i][1] + bb[1], 0.f);
        h0.z = fmaxf(acc[i][2] + bb[2], 0.f);
        h0.w = fmaxf(acc[i][3] + bb[3], 0.f);
        h1.x = fmaxf(acc[i][4] + bb[4], 0.f);
        h1.y = fmaxf(acc[i][5] + bb[5], 0.f);
        h1.z = fmaxf(acc[i][6] + bb[6], 0.f);
        h1.w = fmaxf(acc[i][7] + bb[7], 0.f);
        *(float4*)(As + r * 132 + tx * 8)     = h0;
        *(float4*)(As + r * 132 + tx * 8 + 4) = h1;
    }
    __syncthreads();

    // GEMM2: eo[64,32] = h[64,128] @ W2[128,32]
    const int tx2 = tid & 7, ty2 = tid >> 3;   // 8 x 32 layout, 2 rows x 4 cols each
    float acc2[2][4];
#pragma unroll
    for (int i = 0; i < 2; i++)
#pragma unroll
        for (int j = 0; j < 4; j++) acc2[i][j] = 0.f;
#pragma unroll 8
    for (int k = 0; k < 128; k++) {
        float4 w = *(const float4*)(W2s + k * 32 + tx2 * 4);
        float h0 = As[(ty2 * 2) * 132 + k];
        float h1 = As[(ty2 * 2 + 1) * 132 + k];
        acc2[0][0] = fmaf(h0, w.x, acc2[0][0]);
        acc2[0][1] = fmaf(h0, w.y, acc2[0][1]);
        acc2[0][2] = fmaf(h0, w.z, acc2[0][2]);
        acc2[0][3] = fmaf(h0, w.w, acc2[0][3]);
        acc2[1][0] = fmaf(h1, w.x, acc2[1][0]);
        acc2[1][1] = fmaf(h1, w.y, acc2[1][1]);
        acc2[1][2] = fmaf(h1, w.z, acc2[1][2]);
        acc2[1][3] = fmaf(h1, w.w, acc2[1][3]);
    }
    float bc[4];
    const float* b2e = b2 + e * OD;
#pragma unroll
    for (int j = 0; j < 4; j++) bc[j] = b2e[tx2 * 4 + j];
#pragma unroll
    for (int i = 0; i < 2; i++) {
        int r = ty2 * 2 + i;
        if (r < nvalid) {
            int enc = sEnc[r];
            float w = sW[r];
            float4 o;
            o.x = (acc2[i][0] + bc[0]) * w;
            o.y = (acc2[i][1] + bc[1]) * w;
            o.z = (acc2[i][2] + bc[2]) * w;
            o.w = (acc2[i][3] + bc[3]) * w;
            *(float4*)(g_ys + (size_t)enc * 32 + tx2 * 4) = o;
        }
    }
}

// ---------------- final: out[b] = sum_j y_flat[b][j] * Wout[j] + bout ----------------
__global__ void k_final(const float* __restrict__ Wout, const float* __restrict__ bout,
                        float* __restrict__ out, int out_size) {
    const int tid = threadIdx.x, lane = tid & 31, warp = tid >> 5;
    const int b = blockIdx.x * 8 + warp;
    const int j = lane * 4;
    const int n = b * 4 + (j >> 5);
    const int o = j & 31;
    float4 y0 = *(const float4*)(g_ys + (size_t)(n * 2) * 32 + o);
    float4 y1 = *(const float4*)(g_ys + (size_t)(n * 2 + 1) * 32 + o);
    float4 wv = *(const float4*)(Wout + j);
    float s = (y0.x + y1.x) * wv.x + (y0.y + y1.y) * wv.y +
              (y0.z + y1.z) * wv.z + (y0.w + y1.w) * wv.w;
#pragma unroll
    for (int off = 16; off; off >>= 1) s += __shfl_xor_sync(0xffffffffu, s, off);
    if (lane == 0) out[b] = s + bout[0];
    if (blockIdx.x == 0 && tid == 0)
        for (int i = Bq; i < out_size; i++) out[i] = g_aux;   // aux loss scalar
}

// ---------------- launch ----------------
extern "C" void kernel_launch(void* const* d_in, const int* in_sizes, int n_in,
                              void* d_out, int out_size) {
    const float* x    = (const float*)d_in[0];
    const float* Wq   = (const float*)d_in[1];
    const float* bq   = (const float*)d_in[2];
    const float* Wk   = (const float*)d_in[3];
    const float* bk   = (const float*)d_in[4];
    const float* Wg   = (const float*)d_in[5];
    const float* W1   = (const float*)d_in[6];
    const float* b1   = (const float*)d_in[7];
    const float* W2   = (const float*)d_in[8];
    const float* b2   = (const float*)d_in[9];
    const float* Wout = (const float*)d_in[10];
    const float* bout = (const float*)d_in[11];
    float* out = (float*)d_out;

    const int smProj = (128 * 132 + 128 * 64) * 4;  // 100,352 B
    const int smExp  = 20864 * 4;                   // 83,456 B
    cudaFuncSetAttribute(k_proj,   cudaFuncAttributeMaxDynamicSharedMemorySize, smProj);
    cudaFuncSetAttribute(k_expert, cudaFuncAttributeMaxDynamicSharedMemorySize, smExp);

    void* ptok = nullptr; void* pgate = nullptr;
    cudaGetSymbolAddress(&ptok,  g_tok);
    cudaGetSymbolAddress(&pgate, g_gate);

    k_init<<<1, 32>>>();
    dim3 gp(8, 128);
    k_proj<<<gp, 256, smProj>>>(x, Wq, bq, (float*)ptok);
    k_proj<<<gp, 256, smProj>>>(x, Wk, bk, (float*)pgate);
    k_gate<<<NGB, 256>>>(Wg);
    k_phase2<<<1, 64>>>();
    k_scatter<<<NSLOT / 256, 256>>>();
    k_expert<<<2056, 256, smExp>>>(W1, b1, W2, b2);
    k_final<<<Bq / 8, 256>>>(Wout, bout, out, out_size);
}